// round 14
// baseline (speedup 1.0000x reference)
#include <cuda_runtime.h>
#include <cuda_fp16.h>
#include <cstdint>
#include <math.h>

#define NB   16384
#define ND   2048
#define NH   1024
#define NACT 12
#define NK1  1088   // 1036 padded to 1088 (multiple of 64)
#define NKJ  4096
#define NILV 4096   // interleaved gate/cand width

#define ROWB      144                    // 128B data + 16B pad
#define STAGE_B   (128 * ROWB * 2)       // A + B = 36864
#define STAGES    3
#define GEMM_SMEM (STAGES * STAGE_B)     // 110592

// ---------------- scratch (device globals; no allocation allowed) -------------
__device__ __half g_W1t[(size_t)NH * NK1];      // [N=1024, K=1088]
__device__ __half g_W2t[(size_t)ND * NH];       // [N=2048, K=1024]
__device__ __half g_Wgct[(size_t)NILV * NKJ];   // interleaved [4096, 4096]
__device__ float  g_bi[NILV];                   // interleaved bias (bg,bc)
__device__ __half g_a1h[(size_t)NB * NK1];      // [stoch | a_n | 0] half
__device__ __half g_x1h[(size_t)NB * NH];
__device__ __half g_inph[(size_t)NB * ND];
__device__ __half g_ssmh[(size_t)NB * ND];
__device__ float  g_U[NB * 16];
__device__ __half g_preh[(size_t)NB * ND];      // combine output (half)
__device__ float  g_e[ND];
__device__ float  g_dt[ND];

// ---------------- helpers ----------------
__device__ __forceinline__ void cp16(void* smem, const void* g) {
    uint32_t s = (uint32_t)__cvta_generic_to_shared(smem);
    asm volatile("cp.async.cg.shared.global [%0], [%1], 16;\n" :: "r"(s), "l"(g));
}
__device__ __forceinline__ void cp_commit() { asm volatile("cp.async.commit_group;\n"); }
template<int N> __device__ __forceinline__ void cp_wait() {
    asm volatile("cp.async.wait_group %0;\n" :: "n"(N));
}
__device__ __forceinline__ float softplus_f(float x) {
    return x > 20.f ? x : log1pf(expf(x));
}
__device__ __forceinline__ float sigmoid_f(float x) {
    return 1.f / (1.f + __expf(-x));
}
#define LDSM_X4(R, addr) \
    asm volatile("ldmatrix.sync.aligned.m8n8.x4.shared.b16 {%0,%1,%2,%3}, [%4];" \
                 : "=r"((R)[0]), "=r"((R)[1]), "=r"((R)[2]), "=r"((R)[3]) \
                 : "r"(addr))
#define MMA16816(ACC, A, B0, B1) \
    asm volatile("mma.sync.aligned.m16n8k16.row.col.f32.f16.f16.f32 " \
                 "{%0,%1,%2,%3},{%4,%5,%6,%7},{%8,%9},{%0,%1,%2,%3};\n" \
                 : "+f"((ACC)[0]), "+f"((ACC)[1]), "+f"((ACC)[2]), "+f"((ACC)[3]) \
                 : "r"((A)[0]), "r"((A)[1]), "r"((A)[2]), "r"((A)[3]), \
                   "r"(B0), "r"(B1))

// ---------------- fp16 tensor-core GEMM (BK=64, R8 pipeline structure) --------
// C(M,N) = concat_k[A | A2](half) * Bt(half,[N,K] row-major)^T + bias
// BM=BN=128, BK=64, 256 threads = 8 warps (4 m x 2 n), warp tile 32x64.
// 16 MMA groups/iter (g = kk*4 + jj, kk=0..3), Bf ring slot = g&3 (distance-2),
// Af double-buffered one kk-step ahead. One barrier per iter.
// act: 0 plain (otype 0 f32 / 1 f16), 4 fused gate/cand combine (half out),
//      5 inp(half) + fused ssm epilogue (ssm_out half).
__global__ void __launch_bounds__(256, 2) gemm_fp16(
    const __half* __restrict__ A,  int lda,
    const __half* __restrict__ A2, int lda2, int ksplit,
    const __half* __restrict__ Bt, int ldbt,
    const float* __restrict__ bias,
    void* __restrict__ Co, int ldc,
    int M, int N, int K, int act, int otype,
    const float* __restrict__ auxd,
    const float* __restrict__ Wvp, const float* __restrict__ Uarr,
    const float* __restrict__ evec, const float* __restrict__ dtvec,
    __half* __restrict__ ssm_out)
{
    extern __shared__ char smem[];
    const int tid  = threadIdx.x;
    const int lane = tid & 31;
    const int warp = tid >> 5;
    const int wm   = warp >> 1;   // 0..3
    const int wn   = warp & 1;    // 0..1
    const int gr   = lane >> 2;   // 0..7
    const int q    = lane & 3;    // 0..3

    // grouped rasterization (GROUP_M=8): weight panel L2 reuse
    const int grid_m = M >> 7;
    const int grid_n = N >> 7;
    const int width  = 8 * grid_n;
    const int pid    = blockIdx.x;
    const int group  = pid / width;
    const int first  = group * 8;
    int gm = grid_m - first; if (gm > 8) gm = 8;
    const int pm = first + (pid % width) % gm;
    const int pn = (pid % width) / gm;
    const int m0 = pm << 7;
    const int n0 = pn << 7;

    const int KS = K >> 6;

    // cp.async coords: 128 rows x 8 chunks(16B) per operand; 2 threads/row
    const int crow = tid >> 1;          // 0..127
    const int ch   = (tid & 1) * 4;     // chunk base 0 or 4

    auto load_stage = [&](int ks, int slot) {
        const int k0 = ks << 6;
        char* st  = smem + slot * STAGE_B;
        char* stb = st + 128 * ROWB;
        const __half* Ab; int ld; int ko;
        if (k0 < ksplit) { Ab = A;  ld = lda;  ko = k0; }
        else             { Ab = A2; ld = lda2; ko = k0 - ksplit; }
        const __half* Ar = Ab + (size_t)(m0 + crow) * ld + ko;
#pragma unroll
        for (int p = 0; p < 4; p++)
            cp16(st + crow * ROWB + (ch + p) * 16, Ar + (ch + p) * 8);
        const __half* Br = Bt + (size_t)(n0 + crow) * ldbt + k0;
#pragma unroll
        for (int p = 0; p < 4; p++)
            cp16(stb + crow * ROWB + (ch + p) * 16, Br + (ch + p) * 8);
    };

    // ldmatrix per-thread base addresses
    const uint32_t smem_u = (uint32_t)__cvta_generic_to_shared(smem);
    const uint32_t aBase = smem_u
        + (wm * 32 + (lane & 15)) * ROWB + (lane >> 4) * 16;
    const uint32_t bBase = smem_u + 128 * ROWB
        + (wn * 64 + ((lane & 16) >> 1) + (lane & 7)) * ROWB + ((lane >> 3) & 1) * 16;

    float acc[2][8][4];
#pragma unroll
    for (int i = 0; i < 2; i++)
#pragma unroll
        for (int j = 0; j < 8; j++)
#pragma unroll
            for (int t = 0; t < 4; t++) acc[i][j][t] = 0.f;

    // prefill stages 0..1
#pragma unroll
    for (int s = 0; s < STAGES - 1; s++) {
        if (s < KS) load_stage(s, s);
        cp_commit();
    }

    uint32_t Af[2][2][4];   // [kk&1][i]
    uint32_t Bf[4][4];      // slot = g&3

    for (int ks = 0; ks < KS; ++ks) {
        cp_wait<STAGES - 2>();   // stage ks complete
        __syncthreads();         // all warps done reading slot (ks+2)%STAGES
        const int nxt = ks + STAGES - 1;
        if (nxt < KS) load_stage(nxt, nxt % STAGES);
        cp_commit();

        const uint32_t soff = (uint32_t)(ks % STAGES) * STAGE_B;
        const uint32_t aS = aBase + soff, bS = bBase + soff;

        // warm-up: g0,g1 B frags + kk=0 A frags
        LDSM_X4(Bf[0], bS);
        LDSM_X4(Bf[1], bS + 16 * ROWB);
        LDSM_X4(Af[0][0], aS);
        LDSM_X4(Af[0][1], aS + 16 * ROWB);

#pragma unroll
        for (int g = 0; g < 16; ++g) {
            const int kk = g >> 2, jj = g & 3;
            if (jj == 0 && kk < 3) {   // prefetch next kk's A frags
                LDSM_X4(Af[(kk + 1) & 1][0], aS + (kk + 1) * 32);
                LDSM_X4(Af[(kk + 1) & 1][1], aS + (kk + 1) * 32 + 16 * ROWB);
            }
            if (g + 2 < 16) {          // prefetch B group g+2 (distance 2)
                const int ng = g + 2;
                LDSM_X4(Bf[ng & 3], bS + (ng >> 2) * 32 + (ng & 3) * 16 * ROWB);
            }
            const int cb = g & 3, ai = kk & 1;
#pragma unroll
            for (int p = 0; p < 2; p++) {
                const int j = 2 * jj + p;
                MMA16816(acc[0][j], Af[ai][0], Bf[cb][2 * p], Bf[cb][2 * p + 1]);
                MMA16816(acc[1][j], Af[ai][1], Bf[cb][2 * p], Bf[cb][2 * p + 1]);
            }
        }
    }

    // ---------------- epilogues ----------------
    if (act == 4) {
        __half* Ch = (__half*)Co;
#pragma unroll
        for (int i = 0; i < 2; i++) {
            const int row = m0 + wm * 32 + i * 16 + gr;
#pragma unroll
            for (int j = 0; j < 8; j++) {
                const int col = n0 + wn * 64 + j * 8 + (q << 1);  // even
                const int jc  = col >> 1;
                const float2 ib = *(const float2*)(bias + col);   // (bg, bc)
                const size_t i0 = (size_t)row * ldc + jc;
                const size_t i1 = (size_t)(row + 8) * ldc + jc;
                const float gA = sigmoid_f(acc[i][j][0] + ib.x);
                const float cA = tanhf(acc[i][j][1] + ib.y);
                const float gB = sigmoid_f(acc[i][j][2] + ib.x);
                const float cB = tanhf(acc[i][j][3] + ib.y);
                Ch[i0] = __float2half_rn(gA * cA + (1.f - gA) * auxd[i0]);
                Ch[i1] = __float2half_rn(gB * cB + (1.f - gB) * auxd[i1]);
            }
        }
        return;
    }
    if (act == 5) {
        __half* Ch = (__half*)Co;
#pragma unroll
        for (int i = 0; i < 2; i++) {
            const int row = m0 + wm * 32 + i * 16 + gr;
            float u0[16], u1[16];
            {
                const float4* U0 = (const float4*)(Uarr + (size_t)row * 16);
                const float4* U1 = (const float4*)(Uarr + (size_t)(row + 8) * 16);
#pragma unroll
                for (int r4 = 0; r4 < 4; r4++) {
                    const float4 a = U0[r4], b = U1[r4];
                    u0[r4*4+0]=a.x; u0[r4*4+1]=a.y; u0[r4*4+2]=a.z; u0[r4*4+3]=a.w;
                    u1[r4*4+0]=b.x; u1[r4*4+1]=b.y; u1[r4*4+2]=b.z; u1[r4*4+3]=b.w;
                }
            }
#pragma unroll
            for (int j = 0; j < 8; j++) {
                const int col = n0 + wn * 64 + j * 8 + (q << 1);
                const float2 bv = *(const float2*)(bias + col);
                const float v0 = acc[i][j][0] + bv.x, v1 = acc[i][j][1] + bv.y;
                const float v2 = acc[i][j][2] + bv.x, v3 = acc[i][j][3] + bv.y;
                const size_t i0 = (size_t)row * ldc + col;
                const size_t i1 = (size_t)(row + 8) * ldc + col;
                *(__half2*)(Ch + i0) = __floats2half2_rn(v0, v1);
                *(__half2*)(Ch + i1) = __floats2half2_rn(v2, v3);
                // fused ssm = e*(deter + U@Wv) + dt*inp
                float s0 = 0.f, s1 = 0.f, s2 = 0.f, s3 = 0.f;
#pragma unroll
                for (int r = 0; r < 16; r++) {
                    const float2 wv = *(const float2*)(Wvp + (size_t)r * ND + col);
                    s0 += u0[r] * wv.x; s1 += u0[r] * wv.y;
                    s2 += u1[r] * wv.x; s3 += u1[r] * wv.y;
                }
                const float2 e2  = *(const float2*)(evec + col);
                const float2 dt2 = *(const float2*)(dtvec + col);
                const float2 d0  = *(const float2*)(auxd + i0);
                const float2 d1  = *(const float2*)(auxd + i1);
                *(__half2*)(ssm_out + i0) = __floats2half2_rn(
                    e2.x * (d0.x + s0) + dt2.x * v0,
                    e2.y * (d0.y + s1) + dt2.y * v1);
                *(__half2*)(ssm_out + i1) = __floats2half2_rn(
                    e2.x * (d1.x + s2) + dt2.x * v2,
                    e2.y * (d1.y + s3) + dt2.y * v3);
            }
        }
        return;
    }
#pragma unroll
    for (int i = 0; i < 2; i++) {
        const int row = m0 + wm * 32 + i * 16 + gr;
#pragma unroll
        for (int j = 0; j < 8; j++) {
            const int col = n0 + wn * 64 + j * 8 + (q << 1);
            const float2 bv = *(const float2*)(bias + col);
            const float v0 = acc[i][j][0] + bv.x, v1 = acc[i][j][1] + bv.y;
            const float v2 = acc[i][j][2] + bv.x, v3 = acc[i][j][3] + bv.y;
            if (otype == 0) {
                float* Cf = (float*)Co;
                *(float2*)(Cf + (size_t)row * ldc + col)       = make_float2(v0, v1);
                *(float2*)(Cf + (size_t)(row + 8) * ldc + col) = make_float2(v2, v3);
            } else {
                __half* Ch = (__half*)Co;
                *(__half2*)(Ch + (size_t)row * ldc + col)       = __floats2half2_rn(v0, v1);
                *(__half2*)(Ch + (size_t)(row + 8) * ldc + col) = __floats2half2_rn(v2, v3);
            }
        }
    }
}

// ---------------- prep kernels ----------------
// Build A1 = [stoch | a_n | zeros] in half, [NB, 1088]
__global__ void prep_a1(const float* __restrict__ stoch,
                        const float* __restrict__ action) {
    int idx = blockIdx.x * blockDim.x + threadIdx.x;   // over NB*544 half2
    if (idx >= NB * (NK1 / 2)) return;
    const int b  = idx / (NK1 / 2);
    const int c2 = idx - b * (NK1 / 2);
    __half2 v;
    if (c2 < 512) {
        const float2 s = ((const float2*)(stoch + (size_t)b * 1024))[c2];
        v = __floats2half2_rn(s.x, s.y);
    } else if (c2 < 518) {
        const int a0 = (c2 - 512) * 2;
        const float x = action[b * NACT + a0];
        const float y = action[b * NACT + a0 + 1];
        v = __floats2half2_rn(x / fmaxf(fabsf(x), 1.f), y / fmaxf(fabsf(y), 1.f));
    } else {
        v = __floats2half2_rn(0.f, 0.f);
    }
    ((__half2*)g_a1h)[idx] = v;
}

// Transpose W[K,N] -> Wt[N,Kpad] in half; zero-pad k in [K,Kpad)
__global__ void prep_wt(const float* __restrict__ W, __half* __restrict__ Wt,
                        int K, int N, int Kpad) {
    __shared__ float t[32][33];
    const int kb = blockIdx.x * 32, nb = blockIdx.y * 32;
    const int tx = threadIdx.x, ty = threadIdx.y;   // 32 x 8
#pragma unroll
    for (int i = 0; i < 4; i++) {
        const int kk = kb + ty + i * 8;
        t[ty + i * 8][tx] = (kk < K) ? W[(size_t)kk * N + nb + tx] : 0.f;
    }
    __syncthreads();
#pragma unroll
    for (int i = 0; i < 4; i++) {
        const int nn = nb + ty + i * 8;
        const int kk = kb + tx;
        if (kk < Kpad) Wt[(size_t)nn * Kpad + kk] = __float2half_rn(t[tx][ty + i * 8]);
    }
}

// Interleaved transpose: out row 2j = Wg col j, row 2j+1 = Wc col j.
__global__ void prep_wt_ilv(const float* __restrict__ Wg, const float* __restrict__ Wc,
                            __half* __restrict__ Wt) {
    __shared__ float tg[32][33];
    __shared__ float tc[32][33];
    const int kb = blockIdx.x * 32, nb = blockIdx.y * 32;
    const int tx = threadIdx.x, ty = threadIdx.y;   // 32 x 8
#pragma unroll
    for (int i = 0; i < 4; i++) {
        const int kk = kb + ty + i * 8;
        tg[ty + i * 8][tx] = Wg[(size_t)kk * ND + nb + tx];
        tc[ty + i * 8][tx] = Wc[(size_t)kk * ND + nb + tx];
    }
    __syncthreads();
#pragma unroll
    for (int i = 0; i < 4; i++) {
        const int nn = nb + ty + i * 8;
        const int kk = kb + tx;
        Wt[(size_t)(2 * nn)     * NKJ + kk] = __float2half_rn(tg[tx][ty + i * 8]);
        Wt[(size_t)(2 * nn + 1) * NKJ + kk] = __float2half_rn(tc[tx][ty + i * 8]);
    }
}

__global__ void bias_ilv(const float* __restrict__ bg, const float* __restrict__ bc) {
    int j = blockIdx.x * blockDim.x + threadIdx.x;
    if (j >= ND) return;
    g_bi[2 * j]     = bg[j];
    g_bi[2 * j + 1] = bc[j];
}

__global__ void decay_k(const float* __restrict__ a_log, const float* __restrict__ dt_p) {
    int i = blockIdx.x * blockDim.x + threadIdx.x;
    if (i >= ND) return;
    float dt = softplus_f(dt_p[i]) + 1e-4f;
    float a  = -softplus_f(a_log[i]);
    g_dt[i] = dt;
    g_e[i]  = expf(a * dt);
}

// rmsnorm + silu over g_x1h rows (len 1024), in place (half in/out)
__global__ void __launch_bounds__(256) act1_k(const float* __restrict__ g1) {
    __shared__ float red[8];
    const int b = blockIdx.x, t = threadIdx.x;
    __half2* row = (__half2*)(g_x1h + (size_t)b * NH);
    const __half2 h0 = row[t * 2], h1 = row[t * 2 + 1];
    float2 v0 = __half22float2(h0), v1 = __half22float2(h1);
    float ss = v0.x * v0.x + v0.y * v0.y + v1.x * v1.x + v1.y * v1.y;
#pragma unroll
    for (int o = 16; o > 0; o >>= 1) ss += __shfl_xor_sync(~0u, ss, o);
    if ((t & 31) == 0) red[t >> 5] = ss;
    __syncthreads();
    float tot = 0.f;
#pragma unroll
    for (int w = 0; w < 8; w++) tot += red[w];
    const float scale = rsqrtf(tot * (1.f / NH) + 1e-4f);
    const float4 g = ((const float4*)g1)[t];
    float a0 = v0.x * scale * g.x, a1 = v0.y * scale * g.y;
    float a2 = v1.x * scale * g.z, a3 = v1.y * scale * g.w;
    a0 *= sigmoid_f(a0); a1 *= sigmoid_f(a1);
    a2 *= sigmoid_f(a2); a3 *= sigmoid_f(a3);
    row[t * 2]     = __floats2half2_rn(a0, a1);
    row[t * 2 + 1] = __floats2half2_rn(a2, a3);
}

// U = deter @ Wu (warp per 4 rows, rank 16)
__global__ void __launch_bounds__(256) u_k(const float* __restrict__ deter,
                                           const float* __restrict__ Wu) {
    const int gwarp = (blockIdx.x * blockDim.x + threadIdx.x) >> 5;  // 0..4095
    const int lane  = threadIdx.x & 31;
    const int r0    = gwarp * 4;
    if (r0 >= NB) return;
    const float* dr = deter + (size_t)r0 * ND;
    float acc[4][16];
#pragma unroll
    for (int r = 0; r < 4; r++)
#pragma unroll
        for (int k = 0; k < 16; k++) acc[r][k] = 0.f;
    for (int i = lane; i < ND; i += 32) {
        const float4* wp = (const float4*)(Wu + (size_t)i * 16);
        const float4 w0 = wp[0], w1 = wp[1], w2 = wp[2], w3 = wp[3];
#pragma unroll
        for (int r = 0; r < 4; r++) {
            const float d = dr[(size_t)r * ND + i];
            acc[r][0]  += d * w0.x; acc[r][1]  += d * w0.y;
            acc[r][2]  += d * w0.z; acc[r][3]  += d * w0.w;
            acc[r][4]  += d * w1.x; acc[r][5]  += d * w1.y;
            acc[r][6]  += d * w1.z; acc[r][7]  += d * w1.w;
            acc[r][8]  += d * w2.x; acc[r][9]  += d * w2.y;
            acc[r][10] += d * w2.z; acc[r][11] += d * w2.w;
            acc[r][12] += d * w3.x; acc[r][13] += d * w3.y;
            acc[r][14] += d * w3.z; acc[r][15] += d * w3.w;
        }
    }
#pragma unroll
    for (int r = 0; r < 4; r++)
#pragma unroll
        for (int k = 0; k < 16; k++) {
            float v = acc[r][k];
#pragma unroll
            for (int o = 16; o > 0; o >>= 1) v += __shfl_xor_sync(~0u, v, o);
            if (lane == 0) g_U[(r0 + r) * 16 + k] = v;
        }
}

// final rmsnorm over g_preh rows (len 2048, half) -> out (f32)
__global__ void __launch_bounds__(512) final_k(const float* __restrict__ gn,
                                               float* __restrict__ out) {
    __shared__ float red[16];
    const int b = blockIdx.x, t = threadIdx.x;
    const __half2* row = (const __half2*)(g_preh + (size_t)b * ND);
    const __half2 h0 = row[t * 2], h1 = row[t * 2 + 1];
    const float2 v0 = __half22float2(h0), v1 = __half22float2(h1);
    float ss = v0.x * v0.x + v0.y * v0.y + v1.x * v1.x + v1.y * v1.y;
#pragma unroll
    for (int o = 16; o > 0; o >>= 1) ss += __shfl_xor_sync(~0u, ss, o);
    if ((t & 31) == 0) red[t >> 5] = ss;
    __syncthreads();
    float tot = 0.f;
#pragma unroll
    for (int w = 0; w < 16; w++) tot += red[w];
    const float scale = rsqrtf(tot * (1.f / ND) + 1e-4f);
    const float4 g = ((const float4*)gn)[t];
    float4 o;
    o.x = v0.x * scale * g.x; o.y = v0.y * scale * g.y;
    o.z = v1.x * scale * g.z; o.w = v1.y * scale * g.w;
    ((float4*)(out + (size_t)b * ND))[t] = o;
}

// ---------------- host launcher ----------------
extern "C" void kernel_launch(void* const* d_in, const int* in_sizes, int n_in,
                              void* d_out, int out_size) {
    const float* stoch  = (const float*)d_in[0];
    const float* deter  = (const float*)d_in[1];
    const float* action = (const float*)d_in[2];
    const float* W1     = (const float*)d_in[3];
    const float* b1     = (const float*)d_in[4];
    const float* g1     = (const float*)d_in[5];
    const float* W2     = (const float*)d_in[6];
    const float* b2     = (const float*)d_in[7];
    const float* Wu     = (const float*)d_in[8];
    const float* Wv     = (const float*)d_in[9];
    const float* a_log  = (const float*)d_in[10];
    const float* dt_p   = (const float*)d_in[11];
    const float* Wg     = (const float*)d_in[12];
    const float* bg     = (const float*)d_in[13];
    const float* Wc     = (const float*)d_in[14];
    const float* bc     = (const float*)d_in[15];
    const float* gn     = (const float*)d_in[16];
    float* out = (float*)d_out;

    __half *pW1t, *pW2t, *pWgct, *pA1, *pX1, *pInp, *pSsm, *pPreh;
    float  *pBi, *pU, *pE, *pDt;
    cudaGetSymbolAddress((void**)&pW1t,  g_W1t);
    cudaGetSymbolAddress((void**)&pW2t,  g_W2t);
    cudaGetSymbolAddress((void**)&pWgct, g_Wgct);
    cudaGetSymbolAddress((void**)&pA1,   g_a1h);
    cudaGetSymbolAddress((void**)&pX1,   g_x1h);
    cudaGetSymbolAddress((void**)&pInp,  g_inph);
    cudaGetSymbolAddress((void**)&pSsm,  g_ssmh);
    cudaGetSymbolAddress((void**)&pPreh, g_preh);
    cudaGetSymbolAddress((void**)&pBi,   g_bi);
    cudaGetSymbolAddress((void**)&pU,    g_U);
    cudaGetSymbolAddress((void**)&pE,    g_e);
    cudaGetSymbolAddress((void**)&pDt,   g_dt);

    cudaFuncSetAttribute(gemm_fp16, cudaFuncAttributeMaxDynamicSharedMemorySize, GEMM_SMEM);

    const dim3 tblk(32, 8);

    // 1: A1 = [stoch | a_n | 0] half
    prep_a1<<<(NB * (NK1 / 2) + 255) / 256, 256>>>(stoch, action);
    // 2: W1^T [1024, 1088]
    prep_wt<<<dim3(NK1 / 32, NH / 32), tblk>>>(W1, pW1t, 1036, NH, NK1);
    // 3: interleaved bias
    bias_ilv<<<(ND + 255) / 256, 256>>>(bg, bc);
    // 4: GEMM1  x1 = A1 @ W1 + b1 -> half   (<- ncu profiled slot)
    gemm_fp16<<<(NB >> 7) * (NH >> 7), 256, GEMM_SMEM>>>(
        pA1, NK1, pA1, NK1, NK1, pW1t, NK1, b1, pX1, NH,
        NB, NH, NK1, 0, 1, nullptr, nullptr, nullptr, nullptr, nullptr, nullptr);
    // 5: rmsnorm + silu
    act1_k<<<NB, 256>>>(g1);
    // 6-8: W2^T, decay, low-rank U (all before GEMM2)
    prep_wt<<<dim3(NH / 32, ND / 32), tblk>>>(W2, pW2t, NH, ND, NH);
    decay_k<<<(ND + 255) / 256, 256>>>(a_log, dt_p);
    u_k<<<NB / 32, 256>>>(deter, Wu);
    // 9: GEMM2  inp = x1 @ W2 + b2 -> half, fused ssm -> half
    gemm_fp16<<<(NB >> 7) * (ND >> 7), 256, GEMM_SMEM>>>(
        pX1, NH, pX1, NH, NH, pW2t, NH, b2, pInp, ND,
        NB, ND, NH, 5, 1, deter, Wv, pU, pE, pDt, pSsm);
    // 10: interleaved gate/cand weights
    prep_wt_ilv<<<dim3(NKJ / 32, ND / 32), tblk>>>(Wg, Wc, pWgct);
    // 11: fused gate+cand GEMM -> pre(half) = sig(g)*tanh(c) + (1-sig(g))*deter
    gemm_fp16<<<(NB >> 7) * (NILV >> 7), 256, GEMM_SMEM>>>(
        pSsm, ND, pInp, ND, ND, pWgct, NKJ, pBi, pPreh, ND,
        NB, NILV, NKJ, 4, 0, deter, nullptr, nullptr, nullptr, nullptr, nullptr);
    // 12: out = rmsnorm(pre, gn)
    final_k<<<NB, 512>>>(gn, out);
}

// round 15
// speedup vs baseline: 1.3187x; 1.3187x over previous
#include <cuda_runtime.h>
#include <cuda_fp16.h>
#include <cstdint>
#include <math.h>

#define NB   16384
#define ND   2048
#define NH   1024
#define NACT 12
#define NK1  1056   // 1036 padded to 1056 (multiple of 32)
#define NKJ  4096
#define NILV 4096   // interleaved gate/cand width

#define ROWB      80
#define STAGE_B   20480                // A 128x80B + B 128x80B
#define STAGES    4
#define GEMM_SMEM (STAGES * STAGE_B)   // 81920

// ---------------- scratch (device globals; no allocation allowed) -------------
__device__ __half g_W1t[(size_t)NH * NK1];      // [N=1024, K=1056]
__device__ __half g_W2t[(size_t)ND * NH];       // [N=2048, K=1024]
__device__ __half g_Wgct[(size_t)NILV * NKJ];   // interleaved [4096, 4096]
__device__ float  g_bi[NILV];                   // interleaved bias (bg,bc)
__device__ __half g_a1h[(size_t)NB * NK1];      // [stoch | a_n | 0] half
__device__ __half g_x1h[(size_t)NB * NH];
__device__ __half g_inph[(size_t)NB * ND];
__device__ __half g_ssmh[(size_t)NB * ND];
__device__ float  g_U[NB * 16];
__device__ __half g_preh[(size_t)NB * ND];      // combine output (half)
__device__ float  g_e[ND];
__device__ float  g_dt[ND];

// ---------------- helpers ----------------
__device__ __forceinline__ void cp16(void* smem, const void* g) {
    uint32_t s = (uint32_t)__cvta_generic_to_shared(smem);
    asm volatile("cp.async.cg.shared.global [%0], [%1], 16;\n" :: "r"(s), "l"(g));
}
__device__ __forceinline__ void cp_commit() { asm volatile("cp.async.commit_group;\n"); }
template<int N> __device__ __forceinline__ void cp_wait() {
    asm volatile("cp.async.wait_group %0;\n" :: "n"(N));
}
__device__ __forceinline__ float softplus_f(float x) {
    return x > 20.f ? x : log1pf(expf(x));
}
__device__ __forceinline__ float sigmoid_f(float x) {
    return 1.f / (1.f + __expf(-x));
}
#define LDSM_X4(R, addr) \
    asm volatile("ldmatrix.sync.aligned.m8n8.x4.shared.b16 {%0,%1,%2,%3}, [%4];" \
                 : "=r"((R)[0]), "=r"((R)[1]), "=r"((R)[2]), "=r"((R)[3]) \
                 : "r"(addr))
#define MMA16816(ACC, A, B0, B1) \
    asm volatile("mma.sync.aligned.m16n8k16.row.col.f32.f16.f16.f32 " \
                 "{%0,%1,%2,%3},{%4,%5,%6,%7},{%8,%9},{%0,%1,%2,%3};\n" \
                 : "+f"((ACC)[0]), "+f"((ACC)[1]), "+f"((ACC)[2]), "+f"((ACC)[3]) \
                 : "r"((A)[0]), "r"((A)[1]), "r"((A)[2]), "r"((A)[3]), \
                   "r"(B0), "r"(B1))

// ---------------- fp16 tensor-core GEMM (R8 BK=32 pipeline, templated) --------
// C(M,N) = concat_k[A | A2](half) * Bt(half,[N,K] row-major)^T + bias
// BM=BN=128, BK=32, 256 threads = 8 warps (4 m x 2 n), warp tile 32x64.
// ACT: 0 plain (OTYPE 0 f32 / 1 f16 store), 4 fused gate/cand combine (half),
//      5 inp(half) + fused ssm epilogue (ssm_out half).
template<int ACT, int OTYPE>
__global__ void __launch_bounds__(256, 2) gemm_fp16(
    const __half* __restrict__ A,  int lda,
    const __half* __restrict__ A2, int lda2, int ksplit,
    const __half* __restrict__ Bt, int ldbt,
    const float* __restrict__ bias,
    void* __restrict__ Co, int ldc,
    int M, int N, int K,
    const float* __restrict__ auxd,
    const float* __restrict__ Wvp, const float* __restrict__ Uarr,
    const float* __restrict__ evec, const float* __restrict__ dtvec,
    __half* __restrict__ ssm_out)
{
    extern __shared__ char smem[];
    const int tid  = threadIdx.x;
    const int lane = tid & 31;
    const int warp = tid >> 5;
    const int wm   = warp >> 1;   // 0..3
    const int wn   = warp & 1;    // 0..1
    const int gr   = lane >> 2;   // 0..7
    const int q    = lane & 3;    // 0..3

    // grouped rasterization (GROUP_M=8): weight panel L2 reuse
    const int grid_m = M >> 7;
    const int grid_n = N >> 7;
    const int width  = 8 * grid_n;
    const int pid    = blockIdx.x;
    const int group  = pid / width;
    const int first  = group * 8;
    int gm = grid_m - first; if (gm > 8) gm = 8;
    const int pm = first + (pid % width) % gm;
    const int pn = (pid % width) / gm;
    const int m0 = pm << 7;
    const int n0 = pn << 7;

    const int KS = K >> 5;

    // cp.async coords
    const int crow = tid >> 2;      // 0..63
    const int ckc  = tid & 3;

    auto load_stage = [&](int ks, int slot) {
        const int k0 = ks << 5;
        char* st  = smem + slot * STAGE_B;
        char* stb = st + 10240;
        const __half* Ab; int ld; int ko;
        if (k0 < ksplit) { Ab = A;  ld = lda;  ko = k0; }
        else             { Ab = A2; ld = lda2; ko = k0 - ksplit; }
#pragma unroll
        for (int p = 0; p < 2; p++) {
            const int row = crow + p * 64;
            cp16(st + row * ROWB + ckc * 16,
                 Ab + (size_t)(m0 + row) * ld + ko + ckc * 8);
        }
        const __half* Bb = Bt + (size_t)n0 * ldbt + k0;
#pragma unroll
        for (int p = 0; p < 2; p++) {
            const int row = crow + p * 64;
            cp16(stb + row * ROWB + ckc * 16, Bb + (size_t)row * ldbt + ckc * 8);
        }
    };

    // ldmatrix per-thread base addresses (32-bit shared space)
    const uint32_t smem_u = (uint32_t)__cvta_generic_to_shared(smem);
    const uint32_t aBase = smem_u
        + (wm * 32 + (lane & 15)) * ROWB + (lane >> 4) * 16;
    const uint32_t bBase = smem_u + 10240
        + (wn * 64 + ((lane & 16) >> 1) + (lane & 7)) * ROWB + ((lane >> 3) & 1) * 16;

    float acc[2][8][4];
#pragma unroll
    for (int i = 0; i < 2; i++)
#pragma unroll
        for (int j = 0; j < 8; j++)
#pragma unroll
            for (int t = 0; t < 4; t++) acc[i][j][t] = 0.f;

    // prefill stages 0..2
#pragma unroll
    for (int s = 0; s < STAGES - 1; s++) {
        if (s < KS) load_stage(s, s);
        cp_commit();
    }

    uint32_t Af[2][2][4];   // [kk&1][i]
    uint32_t Bf[4][4];      // slot = g&3

    // prologue: stage 0 resident+visible, then first fragments
    cp_wait<2>();
    __syncthreads();
    LDSM_X4(Af[0][0], aBase);
    LDSM_X4(Af[0][1], aBase + 16 * ROWB);
    LDSM_X4(Bf[0], bBase);                 // g0: kk=0, jj=0
    LDSM_X4(Bf[1], bBase + 16 * ROWB);     // g1

    for (int ks = 0; ks < KS; ++ks) {
        cp_wait<1>();            // stages ks AND ks+1 complete
        __syncthreads();         // visibility + slot-reuse protection
        const int nxt = ks + STAGES - 1;
        if (nxt < KS) load_stage(nxt, nxt & 3);
        cp_commit();

        const uint32_t soff  = (uint32_t)(ks & 3) * STAGE_B;
        const uint32_t nsoff = (ks + 1 < KS) ? (uint32_t)((ks + 1) & 3) * STAGE_B
                                             : soff;   // tail: harmless reload
        const uint32_t aS = aBase + soff, bS = bBase + soff;
        const uint32_t aN = aBase + nsoff, bN = bBase + nsoff;

        // g=0
        LDSM_X4(Bf[2], bS + 2 * 16 * ROWB);
        LDSM_X4(Af[1][0], aS + 32);
        MMA16816(acc[0][0], Af[0][0], Bf[0][0], Bf[0][1]);
        MMA16816(acc[1][0], Af[0][1], Bf[0][0], Bf[0][1]);
        MMA16816(acc[0][1], Af[0][0], Bf[0][2], Bf[0][3]);
        MMA16816(acc[1][1], Af[0][1], Bf[0][2], Bf[0][3]);
        // g=1
        LDSM_X4(Bf[3], bS + 3 * 16 * ROWB);
        LDSM_X4(Af[1][1], aS + 32 + 16 * ROWB);
        MMA16816(acc[0][2], Af[0][0], Bf[1][0], Bf[1][1]);
        MMA16816(acc[1][2], Af[0][1], Bf[1][0], Bf[1][1]);
        MMA16816(acc[0][3], Af[0][0], Bf[1][2], Bf[1][3]);
        MMA16816(acc[1][3], Af[0][1], Bf[1][2], Bf[1][3]);
        // g=2
        LDSM_X4(Bf[0], bS + 32);
        MMA16816(acc[0][4], Af[0][0], Bf[2][0], Bf[2][1]);
        MMA16816(acc[1][4], Af[0][1], Bf[2][0], Bf[2][1]);
        MMA16816(acc[0][5], Af[0][0], Bf[2][2], Bf[2][3]);
        MMA16816(acc[1][5], Af[0][1], Bf[2][2], Bf[2][3]);
        // g=3
        LDSM_X4(Bf[1], bS + 32 + 16 * ROWB);
        MMA16816(acc[0][6], Af[0][0], Bf[3][0], Bf[3][1]);
        MMA16816(acc[1][6], Af[0][1], Bf[3][0], Bf[3][1]);
        MMA16816(acc[0][7], Af[0][0], Bf[3][2], Bf[3][3]);
        MMA16816(acc[1][7], Af[0][1], Bf[3][2], Bf[3][3]);
        // g=4
        LDSM_X4(Bf[2], bS + 32 + 2 * 16 * ROWB);
        LDSM_X4(Af[0][0], aN);
        MMA16816(acc[0][0], Af[1][0], Bf[0][0], Bf[0][1]);
        MMA16816(acc[1][0], Af[1][1], Bf[0][0], Bf[0][1]);
        MMA16816(acc[0][1], Af[1][0], Bf[0][2], Bf[0][3]);
        MMA16816(acc[1][1], Af[1][1], Bf[0][2], Bf[0][3]);
        // g=5
        LDSM_X4(Bf[3], bS + 32 + 3 * 16 * ROWB);
        LDSM_X4(Af[0][1], aN + 16 * ROWB);
        MMA16816(acc[0][2], Af[1][0], Bf[1][0], Bf[1][1]);
        MMA16816(acc[1][2], Af[1][1], Bf[1][0], Bf[1][1]);
        MMA16816(acc[0][3], Af[1][0], Bf[1][2], Bf[1][3]);
        MMA16816(acc[1][3], Af[1][1], Bf[1][2], Bf[1][3]);
        // g=6
        LDSM_X4(Bf[0], bN);
        MMA16816(acc[0][4], Af[1][0], Bf[2][0], Bf[2][1]);
        MMA16816(acc[1][4], Af[1][1], Bf[2][0], Bf[2][1]);
        MMA16816(acc[0][5], Af[1][0], Bf[2][2], Bf[2][3]);
        MMA16816(acc[1][5], Af[1][1], Bf[2][2], Bf[2][3]);
        // g=7
        LDSM_X4(Bf[1], bN + 16 * ROWB);
        MMA16816(acc[0][6], Af[1][0], Bf[3][0], Bf[3][1]);
        MMA16816(acc[1][6], Af[1][1], Bf[3][0], Bf[3][1]);
        MMA16816(acc[0][7], Af[1][0], Bf[3][2], Bf[3][3]);
        MMA16816(acc[1][7], Af[1][1], Bf[3][2], Bf[3][3]);
    }

    // ---------------- epilogues (compile-time selected) ----------------
    if (ACT == 4) {
        __half* Ch = (__half*)Co;
#pragma unroll
        for (int i = 0; i < 2; i++) {
            const int row = m0 + wm * 32 + i * 16 + gr;
#pragma unroll
            for (int j = 0; j < 8; j++) {
                const int col = n0 + wn * 64 + j * 8 + (q << 1);  // even
                const int jc  = col >> 1;
                const float2 ib = *(const float2*)(bias + col);   // (bg, bc)
                const size_t i0 = (size_t)row * ldc + jc;
                const size_t i1 = (size_t)(row + 8) * ldc + jc;
                const float gA = sigmoid_f(acc[i][j][0] + ib.x);
                const float cA = tanhf(acc[i][j][1] + ib.y);
                const float gB = sigmoid_f(acc[i][j][2] + ib.x);
                const float cB = tanhf(acc[i][j][3] + ib.y);
                Ch[i0] = __float2half_rn(gA * cA + (1.f - gA) * auxd[i0]);
                Ch[i1] = __float2half_rn(gB * cB + (1.f - gB) * auxd[i1]);
            }
        }
    } else if (ACT == 5) {
        __half* Ch = (__half*)Co;
#pragma unroll
        for (int i = 0; i < 2; i++) {
            const int row = m0 + wm * 32 + i * 16 + gr;
            float u0[16], u1[16];
            {
                const float4* U0 = (const float4*)(Uarr + (size_t)row * 16);
                const float4* U1 = (const float4*)(Uarr + (size_t)(row + 8) * 16);
#pragma unroll
                for (int r4 = 0; r4 < 4; r4++) {
                    const float4 a = U0[r4], b = U1[r4];
                    u0[r4*4+0]=a.x; u0[r4*4+1]=a.y; u0[r4*4+2]=a.z; u0[r4*4+3]=a.w;
                    u1[r4*4+0]=b.x; u1[r4*4+1]=b.y; u1[r4*4+2]=b.z; u1[r4*4+3]=b.w;
                }
            }
#pragma unroll
            for (int j = 0; j < 8; j++) {
                const int col = n0 + wn * 64 + j * 8 + (q << 1);
                const float2 bv = *(const float2*)(bias + col);
                const float v0 = acc[i][j][0] + bv.x, v1 = acc[i][j][1] + bv.y;
                const float v2 = acc[i][j][2] + bv.x, v3 = acc[i][j][3] + bv.y;
                const size_t i0 = (size_t)row * ldc + col;
                const size_t i1 = (size_t)(row + 8) * ldc + col;
                *(__half2*)(Ch + i0) = __floats2half2_rn(v0, v1);
                *(__half2*)(Ch + i1) = __floats2half2_rn(v2, v3);
                float s0 = 0.f, s1 = 0.f, s2 = 0.f, s3 = 0.f;
#pragma unroll
                for (int r = 0; r < 16; r++) {
                    const float2 wv = *(const float2*)(Wvp + (size_t)r * ND + col);
                    s0 += u0[r] * wv.x; s1 += u0[r] * wv.y;
                    s2 += u1[r] * wv.x; s3 += u1[r] * wv.y;
                }
                const float2 e2  = *(const float2*)(evec + col);
                const float2 dt2 = *(const float2*)(dtvec + col);
                const float2 d0  = *(const float2*)(auxd + i0);
                const float2 d1  = *(const float2*)(auxd + i1);
                *(__half2*)(ssm_out + i0) = __floats2half2_rn(
                    e2.x * (d0.x + s0) + dt2.x * v0,
                    e2.y * (d0.y + s1) + dt2.y * v1);
                *(__half2*)(ssm_out + i1) = __floats2half2_rn(
                    e2.x * (d1.x + s2) + dt2.x * v2,
                    e2.y * (d1.y + s3) + dt2.y * v3);
            }
        }
    } else {
#pragma unroll
        for (int i = 0; i < 2; i++) {
            const int row = m0 + wm * 32 + i * 16 + gr;
#pragma unroll
            for (int j = 0; j < 8; j++) {
                const int col = n0 + wn * 64 + j * 8 + (q << 1);
                const float2 bv = *(const float2*)(bias + col);
                const float v0 = acc[i][j][0] + bv.x, v1 = acc[i][j][1] + bv.y;
                const float v2 = acc[i][j][2] + bv.x, v3 = acc[i][j][3] + bv.y;
                if (OTYPE == 0) {
                    float* Cf = (float*)Co;
                    *(float2*)(Cf + (size_t)row * ldc + col)       = make_float2(v0, v1);
                    *(float2*)(Cf + (size_t)(row + 8) * ldc + col) = make_float2(v2, v3);
                } else {
                    __half* Ch = (__half*)Co;
                    *(__half2*)(Ch + (size_t)row * ldc + col)       = __floats2half2_rn(v0, v1);
                    *(__half2*)(Ch + (size_t)(row + 8) * ldc + col) = __floats2half2_rn(v2, v3);
                }
            }
        }
    }
}

// ---------------- prep kernels ----------------
__global__ void prep_a1(const float* __restrict__ stoch,
                        const float* __restrict__ action) {
    int idx = blockIdx.x * blockDim.x + threadIdx.x;
    if (idx >= NB * (NK1 / 2)) return;
    const int b  = idx / (NK1 / 2);
    const int c2 = idx - b * (NK1 / 2);
    __half2 v;
    if (c2 < 512) {
        const float2 s = ((const float2*)(stoch + (size_t)b * 1024))[c2];
        v = __floats2half2_rn(s.x, s.y);
    } else if (c2 < 518) {
        const int a0 = (c2 - 512) * 2;
        const float x = action[b * NACT + a0];
        const float y = action[b * NACT + a0 + 1];
        v = __floats2half2_rn(x / fmaxf(fabsf(x), 1.f), y / fmaxf(fabsf(y), 1.f));
    } else {
        v = __floats2half2_rn(0.f, 0.f);
    }
    ((__half2*)g_a1h)[idx] = v;
}

__global__ void prep_wt(const float* __restrict__ W, __half* __restrict__ Wt,
                        int K, int N, int Kpad) {
    __shared__ float t[32][33];
    const int kb = blockIdx.x * 32, nb = blockIdx.y * 32;
    const int tx = threadIdx.x, ty = threadIdx.y;
#pragma unroll
    for (int i = 0; i < 4; i++) {
        const int kk = kb + ty + i * 8;
        t[ty + i * 8][tx] = (kk < K) ? W[(size_t)kk * N + nb + tx] : 0.f;
    }
    __syncthreads();
#pragma unroll
    for (int i = 0; i < 4; i++) {
        const int nn = nb + ty + i * 8;
        const int kk = kb + tx;
        if (kk < Kpad) Wt[(size_t)nn * Kpad + kk] = __float2half_rn(t[tx][ty + i * 8]);
    }
}

__global__ void prep_wt_ilv(const float* __restrict__ Wg, const float* __restrict__ Wc,
                            __half* __restrict__ Wt) {
    __shared__ float tg[32][33];
    __shared__ float tc[32][33];
    const int kb = blockIdx.x * 32, nb = blockIdx.y * 32;
    const int tx = threadIdx.x, ty = threadIdx.y;
#pragma unroll
    for (int i = 0; i < 4; i++) {
        const int kk = kb + ty + i * 8;
        tg[ty + i * 8][tx] = Wg[(size_t)kk * ND + nb + tx];
        tc[ty + i * 8][tx] = Wc[(size_t)kk * ND + nb + tx];
    }
    __syncthreads();
#pragma unroll
    for (int i = 0; i < 4; i++) {
        const int nn = nb + ty + i * 8;
        const int kk = kb + tx;
        Wt[(size_t)(2 * nn)     * NKJ + kk] = __float2half_rn(tg[tx][ty + i * 8]);
        Wt[(size_t)(2 * nn + 1) * NKJ + kk] = __float2half_rn(tc[tx][ty + i * 8]);
    }
}

__global__ void bias_ilv(const float* __restrict__ bg, const float* __restrict__ bc) {
    int j = blockIdx.x * blockDim.x + threadIdx.x;
    if (j >= ND) return;
    g_bi[2 * j]     = bg[j];
    g_bi[2 * j + 1] = bc[j];
}

__global__ void decay_k(const float* __restrict__ a_log, const float* __restrict__ dt_p) {
    int i = blockIdx.x * blockDim.x + threadIdx.x;
    if (i >= ND) return;
    float dt = softplus_f(dt_p[i]) + 1e-4f;
    float a  = -softplus_f(a_log[i]);
    g_dt[i] = dt;
    g_e[i]  = expf(a * dt);
}

__global__ void __launch_bounds__(256) act1_k(const float* __restrict__ g1) {
    __shared__ float red[8];
    const int b = blockIdx.x, t = threadIdx.x;
    __half2* row = (__half2*)(g_x1h + (size_t)b * NH);
    const __half2 h0 = row[t * 2], h1 = row[t * 2 + 1];
    float2 v0 = __half22float2(h0), v1 = __half22float2(h1);
    float ss = v0.x * v0.x + v0.y * v0.y + v1.x * v1.x + v1.y * v1.y;
#pragma unroll
    for (int o = 16; o > 0; o >>= 1) ss += __shfl_xor_sync(~0u, ss, o);
    if ((t & 31) == 0) red[t >> 5] = ss;
    __syncthreads();
    float tot = 0.f;
#pragma unroll
    for (int w = 0; w < 8; w++) tot += red[w];
    const float scale = rsqrtf(tot * (1.f / NH) + 1e-4f);
    const float4 g = ((const float4*)g1)[t];
    float a0 = v0.x * scale * g.x, a1 = v0.y * scale * g.y;
    float a2 = v1.x * scale * g.z, a3 = v1.y * scale * g.w;
    a0 *= sigmoid_f(a0); a1 *= sigmoid_f(a1);
    a2 *= sigmoid_f(a2); a3 *= sigmoid_f(a3);
    row[t * 2]     = __floats2half2_rn(a0, a1);
    row[t * 2 + 1] = __floats2half2_rn(a2, a3);
}

__global__ void __launch_bounds__(256) u_k(const float* __restrict__ deter,
                                           const float* __restrict__ Wu) {
    const int gwarp = (blockIdx.x * blockDim.x + threadIdx.x) >> 5;
    const int lane  = threadIdx.x & 31;
    const int r0    = gwarp * 4;
    if (r0 >= NB) return;
    const float* dr = deter + (size_t)r0 * ND;
    float acc[4][16];
#pragma unroll
    for (int r = 0; r < 4; r++)
#pragma unroll
        for (int k = 0; k < 16; k++) acc[r][k] = 0.f;
    for (int i = lane; i < ND; i += 32) {
        const float4* wp = (const float4*)(Wu + (size_t)i * 16);
        const float4 w0 = wp[0], w1 = wp[1], w2 = wp[2], w3 = wp[3];
#pragma unroll
        for (int r = 0; r < 4; r++) {
            const float d = dr[(size_t)r * ND + i];
            acc[r][0]  += d * w0.x; acc[r][1]  += d * w0.y;
            acc[r][2]  += d * w0.z; acc[r][3]  += d * w0.w;
            acc[r][4]  += d * w1.x; acc[r][5]  += d * w1.y;
            acc[r][6]  += d * w1.z; acc[r][7]  += d * w1.w;
            acc[r][8]  += d * w2.x; acc[r][9]  += d * w2.y;
            acc[r][10] += d * w2.z; acc[r][11] += d * w2.w;
            acc[r][12] += d * w3.x; acc[r][13] += d * w3.y;
            acc[r][14] += d * w3.z; acc[r][15] += d * w3.w;
        }
    }
#pragma unroll
    for (int r = 0; r < 4; r++)
#pragma unroll
        for (int k = 0; k < 16; k++) {
            float v = acc[r][k];
#pragma unroll
            for (int o = 16; o > 0; o >>= 1) v += __shfl_xor_sync(~0u, v, o);
            if (lane == 0) g_U[(r0 + r) * 16 + k] = v;
        }
}

__global__ void __launch_bounds__(512) final_k(const float* __restrict__ gn,
                                               float* __restrict__ out) {
    __shared__ float red[16];
    const int b = blockIdx.x, t = threadIdx.x;
    const __half2* row = (const __half2*)(g_preh + (size_t)b * ND);
    const __half2 h0 = row[t * 2], h1 = row[t * 2 + 1];
    const float2 v0 = __half22float2(h0), v1 = __half22float2(h1);
    float ss = v0.x * v0.x + v0.y * v0.y + v1.x * v1.x + v1.y * v1.y;
#pragma unroll
    for (int o = 16; o > 0; o >>= 1) ss += __shfl_xor_sync(~0u, ss, o);
    if ((t & 31) == 0) red[t >> 5] = ss;
    __syncthreads();
    float tot = 0.f;
#pragma unroll
    for (int w = 0; w < 16; w++) tot += red[w];
    const float scale = rsqrtf(tot * (1.f / ND) + 1e-4f);
    const float4 g = ((const float4*)gn)[t];
    float4 o;
    o.x = v0.x * scale * g.x; o.y = v0.y * scale * g.y;
    o.z = v1.x * scale * g.z; o.w = v1.y * scale * g.w;
    ((float4*)(out + (size_t)b * ND))[t] = o;
}

// ---------------- host launcher ----------------
extern "C" void kernel_launch(void* const* d_in, const int* in_sizes, int n_in,
                              void* d_out, int out_size) {
    const float* stoch  = (const float*)d_in[0];
    const float* deter  = (const float*)d_in[1];
    const float* action = (const float*)d_in[2];
    const float* W1     = (const float*)d_in[3];
    const float* b1     = (const float*)d_in[4];
    const float* g1     = (const float*)d_in[5];
    const float* W2     = (const float*)d_in[6];
    const float* b2     = (const float*)d_in[7];
    const float* Wu     = (const float*)d_in[8];
    const float* Wv     = (const float*)d_in[9];
    const float* a_log  = (const float*)d_in[10];
    const float* dt_p   = (const float*)d_in[11];
    const float* Wg     = (const float*)d_in[12];
    const float* bg     = (const float*)d_in[13];
    const float* Wc     = (const float*)d_in[14];
    const float* bc     = (const float*)d_in[15];
    const float* gn     = (const float*)d_in[16];
    float* out = (float*)d_out;

    __half *pW1t, *pW2t, *pWgct, *pA1, *pX1, *pInp, *pSsm, *pPreh;
    float  *pBi, *pU, *pE, *pDt;
    cudaGetSymbolAddress((void**)&pW1t,  g_W1t);
    cudaGetSymbolAddress((void**)&pW2t,  g_W2t);
    cudaGetSymbolAddress((void**)&pWgct, g_Wgct);
    cudaGetSymbolAddress((void**)&pA1,   g_a1h);
    cudaGetSymbolAddress((void**)&pX1,   g_x1h);
    cudaGetSymbolAddress((void**)&pInp,  g_inph);
    cudaGetSymbolAddress((void**)&pSsm,  g_ssmh);
    cudaGetSymbolAddress((void**)&pPreh, g_preh);
    cudaGetSymbolAddress((void**)&pBi,   g_bi);
    cudaGetSymbolAddress((void**)&pU,    g_U);
    cudaGetSymbolAddress((void**)&pE,    g_e);
    cudaGetSymbolAddress((void**)&pDt,   g_dt);

    cudaFuncSetAttribute(gemm_fp16<0,1>, cudaFuncAttributeMaxDynamicSharedMemorySize, GEMM_SMEM);
    cudaFuncSetAttribute(gemm_fp16<5,1>, cudaFuncAttributeMaxDynamicSharedMemorySize, GEMM_SMEM);
    cudaFuncSetAttribute(gemm_fp16<4,0>, cudaFuncAttributeMaxDynamicSharedMemorySize, GEMM_SMEM);

    const dim3 tblk(32, 8);

    // 1: A1 = [stoch | a_n | 0] half
    prep_a1<<<(NB * (NK1 / 2) + 255) / 256, 256>>>(stoch, action);
    // 2: W1^T [1024, 1056]
    prep_wt<<<dim3(NK1 / 32, NH / 32), tblk>>>(W1, pW1t, 1036, NH, NK1);
    // 3: interleaved bias
    bias_ilv<<<(ND + 255) / 256, 256>>>(bg, bc);
    // 4: GEMM1  x1 = A1 @ W1 + b1 -> half   (<- ncu profiled slot)
    gemm_fp16<0,1><<<(NB >> 7) * (NH >> 7), 256, GEMM_SMEM>>>(
        pA1, NK1, pA1, NK1, NK1, pW1t, NK1, b1, pX1, NH,
        NB, NH, NK1, nullptr, nullptr, nullptr, nullptr, nullptr, nullptr);
    // 5: rmsnorm + silu
    act1_k<<<NB, 256>>>(g1);
    // 6-8: W2^T, decay, low-rank U (before GEMM2)
    prep_wt<<<dim3(NH / 32, ND / 32), tblk>>>(W2, pW2t, NH, ND, NH);
    decay_k<<<(ND + 255) / 256, 256>>>(a_log, dt_p);
    u_k<<<NB / 32, 256>>>(deter, Wu);
    // 9: GEMM2  inp = x1 @ W2 + b2 -> half; fused ssm -> half
    gemm_fp16<5,1><<<(NB >> 7) * (ND >> 7), 256, GEMM_SMEM>>>(
        pX1, NH, pX1, NH, NH, pW2t, NH, b2, pInp, ND,
        NB, ND, NH, deter, Wv, pU, pE, pDt, pSsm);
    // 10: interleaved gate/cand weights
    prep_wt_ilv<<<dim3(NKJ / 32, ND / 32), tblk>>>(Wg, Wc, pWgct);
    // 11: fused gate+cand GEMM -> pre(half) = sig(g)*tanh(c) + (1-sig(g))*deter
    gemm_fp16<4,0><<<(NB >> 7) * (NILV >> 7), 256, GEMM_SMEM>>>(
        pSsm, ND, pInp, ND, ND, pWgct, NKJ, pBi, pPreh, ND,
        NB, NILV, NKJ, deter, nullptr, nullptr, nullptr, nullptr, nullptr);
    // 12: out = rmsnorm(pre, gn)
    final_k<<<NB, 512>>>(gn, out);
}

// round 16
// speedup vs baseline: 1.4756x; 1.1190x over previous
#include <cuda_runtime.h>
#include <cuda_fp16.h>
#include <cstdint>
#include <math.h>

#define NB   16384
#define ND   2048
#define NH   1024
#define NACT 12
#define NK1  1056   // 1036 padded to 1056 (multiple of 32)
#define NKJ  4096
#define NILV 4096   // interleaved gate/cand width

#define ROWB      80
#define STAGE_B   20480                // A 128x80B + B 128x80B
#define STAGES    4
#define GEMM_SMEM (STAGES * STAGE_B)   // 81920

// ---------------- scratch (device globals; no allocation allowed) -------------
__device__ __half g_W1t[(size_t)NH * NK1];      // [N=1024, K=1056]
__device__ __half g_W2t[(size_t)ND * NH];       // [N=2048, K=1024]
__device__ __half g_Wgct[(size_t)NILV * NKJ];   // interleaved [4096, 4096]
__device__ float  g_bi[NILV];                   // interleaved bias (bg,bc)
__device__ __half g_a1h[(size_t)NB * NK1];      // [stoch | a_n | 0] half
__device__ __half g_x1h[(size_t)NB * NH];
__device__ __half g_inph[(size_t)NB * ND];
__device__ __half g_ssmh[(size_t)NB * ND];
__device__ float  g_U[NB * 16];
__device__ __half g_preh[(size_t)NB * ND];      // combine output (half)
__device__ float  g_e[ND];
__device__ float  g_dt[ND];

// ---------------- helpers ----------------
__device__ __forceinline__ void cp16(void* smem, const void* g) {
    uint32_t s = (uint32_t)__cvta_generic_to_shared(smem);
    asm volatile("cp.async.cg.shared.global [%0], [%1], 16;\n" :: "r"(s), "l"(g));
}
__device__ __forceinline__ void cp_commit() { asm volatile("cp.async.commit_group;\n"); }
template<int N> __device__ __forceinline__ void cp_wait() {
    asm volatile("cp.async.wait_group %0;\n" :: "n"(N));
}
__device__ __forceinline__ float softplus_f(float x) {
    return x > 20.f ? x : log1pf(expf(x));
}
__device__ __forceinline__ float sigmoid_f(float x) {
    return 1.f / (1.f + __expf(-x));
}
#define LDSM_X4(R, addr) \
    asm volatile("ldmatrix.sync.aligned.m8n8.x4.shared.b16 {%0,%1,%2,%3}, [%4];" \
                 : "=r"((R)[0]), "=r"((R)[1]), "=r"((R)[2]), "=r"((R)[3]) \
                 : "r"(addr))
#define MMA16816(ACC, A, B0, B1) \
    asm volatile("mma.sync.aligned.m16n8k16.row.col.f32.f16.f16.f32 " \
                 "{%0,%1,%2,%3},{%4,%5,%6,%7},{%8,%9},{%0,%1,%2,%3};\n" \
                 : "+f"((ACC)[0]), "+f"((ACC)[1]), "+f"((ACC)[2]), "+f"((ACC)[3]) \
                 : "r"((A)[0]), "r"((A)[1]), "r"((A)[2]), "r"((A)[3]), \
                   "r"(B0), "r"(B1))

// ---------------- fp16 tensor-core GEMM (R8 BK=32 pipeline, templated) --------
// C(M,N) = concat_k[A | A2](half) * Bt(half,[N,K] row-major)^T + bias
// BM=BN=128, BK=32, 256 threads = 8 warps (4 m x 2 n), warp tile 32x64.
// ACT: 0 plain (OTYPE 0 f32 / 1 f16 store), 4 fused gate/cand combine (half).
template<int ACT, int OTYPE>
__global__ void __launch_bounds__(256, 2) gemm_fp16(
    const __half* __restrict__ A,  int lda,
    const __half* __restrict__ A2, int lda2, int ksplit,
    const __half* __restrict__ Bt, int ldbt,
    const float* __restrict__ bias,
    void* __restrict__ Co, int ldc,
    int M, int N, int K,
    const float* __restrict__ auxd)
{
    extern __shared__ char smem[];
    const int tid  = threadIdx.x;
    const int lane = tid & 31;
    const int warp = tid >> 5;
    const int wm   = warp >> 1;   // 0..3
    const int wn   = warp & 1;    // 0..1
    const int gr   = lane >> 2;   // 0..7
    const int q    = lane & 3;    // 0..3

    // grouped rasterization (GROUP_M=8): weight panel L2 reuse
    const int grid_m = M >> 7;
    const int grid_n = N >> 7;
    const int width  = 8 * grid_n;
    const int pid    = blockIdx.x;
    const int group  = pid / width;
    const int first  = group * 8;
    int gm = grid_m - first; if (gm > 8) gm = 8;
    const int pm = first + (pid % width) % gm;
    const int pn = (pid % width) / gm;
    const int m0 = pm << 7;
    const int n0 = pn << 7;

    const int KS = K >> 5;

    // cp.async coords
    const int crow = tid >> 2;      // 0..63
    const int ckc  = tid & 3;

    auto load_stage = [&](int ks, int slot) {
        const int k0 = ks << 5;
        char* st  = smem + slot * STAGE_B;
        char* stb = st + 10240;
        const __half* Ab; int ld; int ko;
        if (k0 < ksplit) { Ab = A;  ld = lda;  ko = k0; }
        else             { Ab = A2; ld = lda2; ko = k0 - ksplit; }
#pragma unroll
        for (int p = 0; p < 2; p++) {
            const int row = crow + p * 64;
            cp16(st + row * ROWB + ckc * 16,
                 Ab + (size_t)(m0 + row) * ld + ko + ckc * 8);
        }
        const __half* Bb = Bt + (size_t)n0 * ldbt + k0;
#pragma unroll
        for (int p = 0; p < 2; p++) {
            const int row = crow + p * 64;
            cp16(stb + row * ROWB + ckc * 16, Bb + (size_t)row * ldbt + ckc * 8);
        }
    };

    // ldmatrix per-thread base addresses (32-bit shared space)
    const uint32_t smem_u = (uint32_t)__cvta_generic_to_shared(smem);
    const uint32_t aBase = smem_u
        + (wm * 32 + (lane & 15)) * ROWB + (lane >> 4) * 16;
    const uint32_t bBase = smem_u + 10240
        + (wn * 64 + ((lane & 16) >> 1) + (lane & 7)) * ROWB + ((lane >> 3) & 1) * 16;

    float acc[2][8][4];
#pragma unroll
    for (int i = 0; i < 2; i++)
#pragma unroll
        for (int j = 0; j < 8; j++)
#pragma unroll
            for (int t = 0; t < 4; t++) acc[i][j][t] = 0.f;

    // prefill stages 0..2
#pragma unroll
    for (int s = 0; s < STAGES - 1; s++) {
        if (s < KS) load_stage(s, s);
        cp_commit();
    }

    uint32_t Af[2][2][4];   // [kk&1][i]
    uint32_t Bf[4][4];      // slot = g&3

    // prologue: stage 0 resident+visible, then first fragments
    cp_wait<2>();
    __syncthreads();
    LDSM_X4(Af[0][0], aBase);
    LDSM_X4(Af[0][1], aBase + 16 * ROWB);
    LDSM_X4(Bf[0], bBase);                 // g0: kk=0, jj=0
    LDSM_X4(Bf[1], bBase + 16 * ROWB);     // g1

    for (int ks = 0; ks < KS; ++ks) {
        cp_wait<1>();            // stages ks AND ks+1 complete
        __syncthreads();         // visibility + slot-reuse protection
        const int nxt = ks + STAGES - 1;
        if (nxt < KS) load_stage(nxt, nxt & 3);
        cp_commit();

        const uint32_t soff  = (uint32_t)(ks & 3) * STAGE_B;
        const uint32_t nsoff = (ks + 1 < KS) ? (uint32_t)((ks + 1) & 3) * STAGE_B
                                             : soff;   // tail: harmless reload
        const uint32_t aS = aBase + soff, bS = bBase + soff;
        const uint32_t aN = aBase + nsoff, bN = bBase + nsoff;

        // g=0
        LDSM_X4(Bf[2], bS + 2 * 16 * ROWB);
        LDSM_X4(Af[1][0], aS + 32);
        MMA16816(acc[0][0], Af[0][0], Bf[0][0], Bf[0][1]);
        MMA16816(acc[1][0], Af[0][1], Bf[0][0], Bf[0][1]);
        MMA16816(acc[0][1], Af[0][0], Bf[0][2], Bf[0][3]);
        MMA16816(acc[1][1], Af[0][1], Bf[0][2], Bf[0][3]);
        // g=1
        LDSM_X4(Bf[3], bS + 3 * 16 * ROWB);
        LDSM_X4(Af[1][1], aS + 32 + 16 * ROWB);
        MMA16816(acc[0][2], Af[0][0], Bf[1][0], Bf[1][1]);
        MMA16816(acc[1][2], Af[0][1], Bf[1][0], Bf[1][1]);
        MMA16816(acc[0][3], Af[0][0], Bf[1][2], Bf[1][3]);
        MMA16816(acc[1][3], Af[0][1], Bf[1][2], Bf[1][3]);
        // g=2
        LDSM_X4(Bf[0], bS + 32);
        MMA16816(acc[0][4], Af[0][0], Bf[2][0], Bf[2][1]);
        MMA16816(acc[1][4], Af[0][1], Bf[2][0], Bf[2][1]);
        MMA16816(acc[0][5], Af[0][0], Bf[2][2], Bf[2][3]);
        MMA16816(acc[1][5], Af[0][1], Bf[2][2], Bf[2][3]);
        // g=3
        LDSM_X4(Bf[1], bS + 32 + 16 * ROWB);
        MMA16816(acc[0][6], Af[0][0], Bf[3][0], Bf[3][1]);
        MMA16816(acc[1][6], Af[0][1], Bf[3][0], Bf[3][1]);
        MMA16816(acc[0][7], Af[0][0], Bf[3][2], Bf[3][3]);
        MMA16816(acc[1][7], Af[0][1], Bf[3][2], Bf[3][3]);
        // g=4
        LDSM_X4(Bf[2], bS + 32 + 2 * 16 * ROWB);
        LDSM_X4(Af[0][0], aN);
        MMA16816(acc[0][0], Af[1][0], Bf[0][0], Bf[0][1]);
        MMA16816(acc[1][0], Af[1][1], Bf[0][0], Bf[0][1]);
        MMA16816(acc[0][1], Af[1][0], Bf[0][2], Bf[0][3]);
        MMA16816(acc[1][1], Af[1][1], Bf[0][2], Bf[0][3]);
        // g=5
        LDSM_X4(Bf[3], bS + 32 + 3 * 16 * ROWB);
        LDSM_X4(Af[0][1], aN + 16 * ROWB);
        MMA16816(acc[0][2], Af[1][0], Bf[1][0], Bf[1][1]);
        MMA16816(acc[1][2], Af[1][1], Bf[1][0], Bf[1][1]);
        MMA16816(acc[0][3], Af[1][0], Bf[1][2], Bf[1][3]);
        MMA16816(acc[1][3], Af[1][1], Bf[1][2], Bf[1][3]);
        // g=6
        LDSM_X4(Bf[0], bN);
        MMA16816(acc[0][4], Af[1][0], Bf[2][0], Bf[2][1]);
        MMA16816(acc[1][4], Af[1][1], Bf[2][0], Bf[2][1]);
        MMA16816(acc[0][5], Af[1][0], Bf[2][2], Bf[2][3]);
        MMA16816(acc[1][5], Af[1][1], Bf[2][2], Bf[2][3]);
        // g=7
        LDSM_X4(Bf[1], bN + 16 * ROWB);
        MMA16816(acc[0][6], Af[1][0], Bf[3][0], Bf[3][1]);
        MMA16816(acc[1][6], Af[1][1], Bf[3][0], Bf[3][1]);
        MMA16816(acc[0][7], Af[1][0], Bf[3][2], Bf[3][3]);
        MMA16816(acc[1][7], Af[1][1], Bf[3][2], Bf[3][3]);
    }

    // ---------------- epilogues (compile-time selected) ----------------
    if (ACT == 4) {
        __half* Ch = (__half*)Co;
#pragma unroll
        for (int i = 0; i < 2; i++) {
            const int row = m0 + wm * 32 + i * 16 + gr;
#pragma unroll
            for (int j = 0; j < 8; j++) {
                const int col = n0 + wn * 64 + j * 8 + (q << 1);  // even
                const int jc  = col >> 1;
                const float2 ib = *(const float2*)(bias + col);   // (bg, bc)
                const size_t i0 = (size_t)row * ldc + jc;
                const size_t i1 = (size_t)(row + 8) * ldc + jc;
                const float gA = sigmoid_f(acc[i][j][0] + ib.x);
                const float cA = tanhf(acc[i][j][1] + ib.y);
                const float gB = sigmoid_f(acc[i][j][2] + ib.x);
                const float cB = tanhf(acc[i][j][3] + ib.y);
                Ch[i0] = __float2half_rn(gA * cA + (1.f - gA) * auxd[i0]);
                Ch[i1] = __float2half_rn(gB * cB + (1.f - gB) * auxd[i1]);
            }
        }
    } else {
#pragma unroll
        for (int i = 0; i < 2; i++) {
            const int row = m0 + wm * 32 + i * 16 + gr;
#pragma unroll
            for (int j = 0; j < 8; j++) {
                const int col = n0 + wn * 64 + j * 8 + (q << 1);
                const float2 bv = *(const float2*)(bias + col);
                const float v0 = acc[i][j][0] + bv.x, v1 = acc[i][j][1] + bv.y;
                const float v2 = acc[i][j][2] + bv.x, v3 = acc[i][j][3] + bv.y;
                if (OTYPE == 0) {
                    float* Cf = (float*)Co;
                    *(float2*)(Cf + (size_t)row * ldc + col)       = make_float2(v0, v1);
                    *(float2*)(Cf + (size_t)(row + 8) * ldc + col) = make_float2(v2, v3);
                } else {
                    __half* Ch = (__half*)Co;
                    *(__half2*)(Ch + (size_t)row * ldc + col)       = __floats2half2_rn(v0, v1);
                    *(__half2*)(Ch + (size_t)(row + 8) * ldc + col) = __floats2half2_rn(v2, v3);
                }
            }
        }
    }
}

// ---------------- prep kernels ----------------
__global__ void prep_a1(const float* __restrict__ stoch,
                        const float* __restrict__ action) {
    int idx = blockIdx.x * blockDim.x + threadIdx.x;
    if (idx >= NB * (NK1 / 2)) return;
    const int b  = idx / (NK1 / 2);
    const int c2 = idx - b * (NK1 / 2);
    __half2 v;
    if (c2 < 512) {
        const float2 s = ((const float2*)(stoch + (size_t)b * 1024))[c2];
        v = __floats2half2_rn(s.x, s.y);
    } else if (c2 < 518) {
        const int a0 = (c2 - 512) * 2;
        const float x = action[b * NACT + a0];
        const float y = action[b * NACT + a0 + 1];
        v = __floats2half2_rn(x / fmaxf(fabsf(x), 1.f), y / fmaxf(fabsf(y), 1.f));
    } else {
        v = __floats2half2_rn(0.f, 0.f);
    }
    ((__half2*)g_a1h)[idx] = v;
}

__global__ void prep_wt(const float* __restrict__ W, __half* __restrict__ Wt,
                        int K, int N, int Kpad) {
    __shared__ float t[32][33];
    const int kb = blockIdx.x * 32, nb = blockIdx.y * 32;
    const int tx = threadIdx.x, ty = threadIdx.y;
#pragma unroll
    for (int i = 0; i < 4; i++) {
        const int kk = kb + ty + i * 8;
        t[ty + i * 8][tx] = (kk < K) ? W[(size_t)kk * N + nb + tx] : 0.f;
    }
    __syncthreads();
#pragma unroll
    for (int i = 0; i < 4; i++) {
        const int nn = nb + ty + i * 8;
        const int kk = kb + tx;
        if (kk < Kpad) Wt[(size_t)nn * Kpad + kk] = __float2half_rn(t[tx][ty + i * 8]);
    }
}

__global__ void prep_wt_ilv(const float* __restrict__ Wg, const float* __restrict__ Wc,
                            __half* __restrict__ Wt) {
    __shared__ float tg[32][33];
    __shared__ float tc[32][33];
    const int kb = blockIdx.x * 32, nb = blockIdx.y * 32;
    const int tx = threadIdx.x, ty = threadIdx.y;
#pragma unroll
    for (int i = 0; i < 4; i++) {
        const int kk = kb + ty + i * 8;
        tg[ty + i * 8][tx] = Wg[(size_t)kk * ND + nb + tx];
        tc[ty + i * 8][tx] = Wc[(size_t)kk * ND + nb + tx];
    }
    __syncthreads();
#pragma unroll
    for (int i = 0; i < 4; i++) {
        const int nn = nb + ty + i * 8;
        const int kk = kb + tx;
        Wt[(size_t)(2 * nn)     * NKJ + kk] = __float2half_rn(tg[tx][ty + i * 8]);
        Wt[(size_t)(2 * nn + 1) * NKJ + kk] = __float2half_rn(tc[tx][ty + i * 8]);
    }
}

__global__ void bias_ilv(const float* __restrict__ bg, const float* __restrict__ bc) {
    int j = blockIdx.x * blockDim.x + threadIdx.x;
    if (j >= ND) return;
    g_bi[2 * j]     = bg[j];
    g_bi[2 * j + 1] = bc[j];
}

__global__ void decay_k(const float* __restrict__ a_log, const float* __restrict__ dt_p) {
    int i = blockIdx.x * blockDim.x + threadIdx.x;
    if (i >= ND) return;
    float dt = softplus_f(dt_p[i]) + 1e-4f;
    float a  = -softplus_f(a_log[i]);
    g_dt[i] = dt;
    g_e[i]  = expf(a * dt);
}

__global__ void __launch_bounds__(256) act1_k(const float* __restrict__ g1) {
    __shared__ float red[8];
    const int b = blockIdx.x, t = threadIdx.x;
    __half2* row = (__half2*)(g_x1h + (size_t)b * NH);
    const __half2 h0 = row[t * 2], h1 = row[t * 2 + 1];
    float2 v0 = __half22float2(h0), v1 = __half22float2(h1);
    float ss = v0.x * v0.x + v0.y * v0.y + v1.x * v1.x + v1.y * v1.y;
#pragma unroll
    for (int o = 16; o > 0; o >>= 1) ss += __shfl_xor_sync(~0u, ss, o);
    if ((t & 31) == 0) red[t >> 5] = ss;
    __syncthreads();
    float tot = 0.f;
#pragma unroll
    for (int w = 0; w < 8; w++) tot += red[w];
    const float scale = rsqrtf(tot * (1.f / NH) + 1e-4f);
    const float4 g = ((const float4*)g1)[t];
    float a0 = v0.x * scale * g.x, a1 = v0.y * scale * g.y;
    float a2 = v1.x * scale * g.z, a3 = v1.y * scale * g.w;
    a0 *= sigmoid_f(a0); a1 *= sigmoid_f(a1);
    a2 *= sigmoid_f(a2); a3 *= sigmoid_f(a3);
    row[t * 2]     = __floats2half2_rn(a0, a1);
    row[t * 2 + 1] = __floats2half2_rn(a2, a3);
}

__global__ void __launch_bounds__(256) u_k(const float* __restrict__ deter,
                                           const float* __restrict__ Wu) {
    const int gwarp = (blockIdx.x * blockDim.x + threadIdx.x) >> 5;
    const int lane  = threadIdx.x & 31;
    const int r0    = gwarp * 4;
    if (r0 >= NB) return;
    const float* dr = deter + (size_t)r0 * ND;
    float acc[4][16];
#pragma unroll
    for (int r = 0; r < 4; r++)
#pragma unroll
        for (int k = 0; k < 16; k++) acc[r][k] = 0.f;
    for (int i = lane; i < ND; i += 32) {
        const float4* wp = (const float4*)(Wu + (size_t)i * 16);
        const float4 w0 = wp[0], w1 = wp[1], w2 = wp[2], w3 = wp[3];
#pragma unroll
        for (int r = 0; r < 4; r++) {
            const float d = dr[(size_t)r * ND + i];
            acc[r][0]  += d * w0.x; acc[r][1]  += d * w0.y;
            acc[r][2]  += d * w0.z; acc[r][3]  += d * w0.w;
            acc[r][4]  += d * w1.x; acc[r][5]  += d * w1.y;
            acc[r][6]  += d * w1.z; acc[r][7]  += d * w1.w;
            acc[r][8]  += d * w2.x; acc[r][9]  += d * w2.y;
            acc[r][10] += d * w2.z; acc[r][11] += d * w2.w;
            acc[r][12] += d * w3.x; acc[r][13] += d * w3.y;
            acc[r][14] += d * w3.z; acc[r][15] += d * w3.w;
        }
    }
#pragma unroll
    for (int r = 0; r < 4; r++)
#pragma unroll
        for (int k = 0; k < 16; k++) {
            float v = acc[r][k];
#pragma unroll
            for (int o = 16; o > 0; o >>= 1) v += __shfl_xor_sync(~0u, v, o);
            if (lane == 0) g_U[(r0 + r) * 16 + k] = v;
        }
}

// ssm = e*(deter + U@Wv) + dt*inp -> half
__global__ void __launch_bounds__(256) ssm_k(const float* __restrict__ deter,
                                             const float* __restrict__ Wv) {
    __shared__ float wv[16][256];
    __shared__ float us[32][16];
    const int tx = threadIdx.x;
    const int c  = blockIdx.x * 256 + tx;
    const int b0 = blockIdx.y * 32;
#pragma unroll
    for (int r = 0; r < 16; r++) wv[r][tx] = Wv[(size_t)r * ND + c];
    us[tx >> 4][tx & 15] = g_U[(b0 + (tx >> 4)) * 16 + (tx & 15)];
    {
        const int t2 = tx + 256;
        us[t2 >> 4][t2 & 15] = g_U[(b0 + (t2 >> 4)) * 16 + (t2 & 15)];
    }
    __syncthreads();
    const float e = g_e[c], dt = g_dt[c];
#pragma unroll 4
    for (int r2 = 0; r2 < 32; r2++) {
        const int b = b0 + r2;
        float m = deter[(size_t)b * ND + c];
#pragma unroll
        for (int r = 0; r < 16; r++) m += us[r2][r] * wv[r][tx];
        const float inp = __half2float(g_inph[(size_t)b * ND + c]);
        g_ssmh[(size_t)b * ND + c] = __float2half_rn(e * m + dt * inp);
    }
}

__global__ void __launch_bounds__(512) final_k(const float* __restrict__ gn,
                                               float* __restrict__ out) {
    __shared__ float red[16];
    const int b = blockIdx.x, t = threadIdx.x;
    const __half2* row = (const __half2*)(g_preh + (size_t)b * ND);
    const __half2 h0 = row[t * 2], h1 = row[t * 2 + 1];
    const float2 v0 = __half22float2(h0), v1 = __half22float2(h1);
    float ss = v0.x * v0.x + v0.y * v0.y + v1.x * v1.x + v1.y * v1.y;
#pragma unroll
    for (int o = 16; o > 0; o >>= 1) ss += __shfl_xor_sync(~0u, ss, o);
    if ((t & 31) == 0) red[t >> 5] = ss;
    __syncthreads();
    float tot = 0.f;
#pragma unroll
    for (int w = 0; w < 16; w++) tot += red[w];
    const float scale = rsqrtf(tot * (1.f / ND) + 1e-4f);
    const float4 g = ((const float4*)gn)[t];
    float4 o;
    o.x = v0.x * scale * g.x; o.y = v0.y * scale * g.y;
    o.z = v1.x * scale * g.z; o.w = v1.y * scale * g.w;
    ((float4*)(out + (size_t)b * ND))[t] = o;
}

// ---------------- host launcher ----------------
extern "C" void kernel_launch(void* const* d_in, const int* in_sizes, int n_in,
                              void* d_out, int out_size) {
    const float* stoch  = (const float*)d_in[0];
    const float* deter  = (const float*)d_in[1];
    const float* action = (const float*)d_in[2];
    const float* W1     = (const float*)d_in[3];
    const float* b1     = (const float*)d_in[4];
    const float* g1     = (const float*)d_in[5];
    const float* W2     = (const float*)d_in[6];
    const float* b2     = (const float*)d_in[7];
    const float* Wu     = (const float*)d_in[8];
    const float* Wv     = (const float*)d_in[9];
    const float* a_log  = (const float*)d_in[10];
    const float* dt_p   = (const float*)d_in[11];
    const float* Wg     = (const float*)d_in[12];
    const float* bg     = (const float*)d_in[13];
    const float* Wc     = (const float*)d_in[14];
    const float* bc     = (const float*)d_in[15];
    const float* gn     = (const float*)d_in[16];
    float* out = (float*)d_out;

    __half *pW1t, *pW2t, *pWgct, *pA1, *pX1, *pInp, *pSsm, *pPreh;
    float  *pBi;
    cudaGetSymbolAddress((void**)&pW1t,  g_W1t);
    cudaGetSymbolAddress((void**)&pW2t,  g_W2t);
    cudaGetSymbolAddress((void**)&pWgct, g_Wgct);
    cudaGetSymbolAddress((void**)&pA1,   g_a1h);
    cudaGetSymbolAddress((void**)&pX1,   g_x1h);
    cudaGetSymbolAddress((void**)&pInp,  g_inph);
    cudaGetSymbolAddress((void**)&pSsm,  g_ssmh);
    cudaGetSymbolAddress((void**)&pPreh, g_preh);
    cudaGetSymbolAddress((void**)&pBi,   g_bi);

    cudaFuncSetAttribute(gemm_fp16<0,1>, cudaFuncAttributeMaxDynamicSharedMemorySize, GEMM_SMEM);
    cudaFuncSetAttribute(gemm_fp16<4,0>, cudaFuncAttributeMaxDynamicSharedMemorySize, GEMM_SMEM);

    const dim3 tblk(32, 8);

    // 1: A1 = [stoch | a_n | 0] half
    prep_a1<<<(NB * (NK1 / 2) + 255) / 256, 256>>>(stoch, action);
    // 2: W1^T [1024, 1056]
    prep_wt<<<dim3(NK1 / 32, NH / 32), tblk>>>(W1, pW1t, 1036, NH, NK1);
    // 3: interleaved bias
    bias_ilv<<<(ND + 255) / 256, 256>>>(bg, bc);
    // 4: GEMM1  x1 = A1 @ W1 + b1 -> half   (<- ncu profiled slot)
    gemm_fp16<0,1><<<(NB >> 7) * (NH >> 7), 256, GEMM_SMEM>>>(
        pA1, NK1, pA1, NK1, NK1, pW1t, NK1, b1, pX1, NH,
        NB, NH, NK1, nullptr);
    // 5: rmsnorm + silu
    act1_k<<<NB, 256>>>(g1);
    // 6: W2^T
    prep_wt<<<dim3(NH / 32, ND / 32), tblk>>>(W2, pW2t, NH, ND, NH);
    // 7: GEMM2  inp = x1 @ W2 + b2 -> half
    gemm_fp16<0,1><<<(NB >> 7) * (ND >> 7), 256, GEMM_SMEM>>>(
        pX1, NH, pX1, NH, NH, pW2t, NH, b2, pInp, ND,
        NB, ND, NH, nullptr);
    // 8: interleaved gate/cand weights
    prep_wt_ilv<<<dim3(NKJ / 32, ND / 32), tblk>>>(Wg, Wc, pWgct);
    // 9-11: decay, low-rank mix, ssm
    decay_k<<<(ND + 255) / 256, 256>>>(a_log, dt_p);
    u_k<<<NB / 32, 256>>>(deter, Wu);
    ssm_k<<<dim3(ND / 256, NB / 32), 256>>>(deter, Wv);
    // 12: fused gate+cand GEMM -> pre(half) = sig(g)*tanh(c) + (1-sig(g))*deter
    gemm_fp16<4,0><<<(NB >> 7) * (NILV >> 7), 256, GEMM_SMEM>>>(
        pSsm, ND, pInp, ND, ND, pWgct, NKJ, pBi, pPreh, ND,
        NB, NILV, NKJ, deter);
    // 13: out = rmsnorm(pre, gn)
    final_k<<<NB, 512>>>(gn, out);
}